// round 15
// baseline (speedup 1.0000x reference)
#include <cuda_runtime.h>
#include <cuda_bf16.h>
#include <math.h>
#include <stdint.h>

#define TOKENS   131072
#define CDIM     192
#define NHEADS   6
#define HD       32
#define NWIN     2048
#define HIDDEN   768

// ---- scratch ----
__device__ __align__(16) __nv_bfloat16 g_winln[TOKENS * CDIM];
__device__ __align__(16) float         g_x2   [TOKENS * CDIM];
__device__ __align__(16) __nv_bfloat16 g_h2   [TOKENS * CDIM];
__device__ __align__(16) __nv_bfloat16 g_mlp  [TOKENS * HIDDEN];
__device__ __align__(16) __nv_bfloat16 g_qkvw_t[3 * CDIM * CDIM];
__device__ __align__(16) __nv_bfloat16 g_projw_t[CDIM * CDIM];
__device__ __align__(16) __nv_bfloat16 g_w1_t[HIDDEN * CDIM];
__device__ __align__(16) __nv_bfloat16 g_w2_t[CDIM * HIDDEN];

__device__ __forceinline__ int win_to_tok(int t) {
    int w = t >> 6, n = t & 63;
    int b  = w >> 8;
    int wi = (w >> 4) & 15;
    int wj = w & 15;
    int r = n >> 3, c = n & 7;
    int row = (wi * 8 + r + 4) & 127;
    int col = (wj * 8 + c + 4) & 127;
    return (b << 14) + (row << 7) + col;
}

// ---- helpers ----
__device__ __forceinline__ unsigned scvta(const void* p) {
    return (unsigned)__cvta_generic_to_shared(p);
}
__device__ __forceinline__ void cp16(void* dst, const void* src) {
    asm volatile("cp.async.cg.shared.global [%0], [%1], 16;" :: "r"(scvta(dst)), "l"(src));
}
__device__ __forceinline__ void cp16s(unsigned dst, const void* src) {
    asm volatile("cp.async.cg.shared.global [%0], [%1], 16;" :: "r"(dst), "l"(src));
}
__device__ __forceinline__ void cp_commit() { asm volatile("cp.async.commit_group;"); }
template <int N>
__device__ __forceinline__ void cp_wait() { asm volatile("cp.async.wait_group %0;" :: "n"(N)); }

__device__ __forceinline__ void ldsm4(unsigned* r, unsigned addr) {
    asm volatile("ldmatrix.sync.aligned.m8n8.x4.shared.b16 {%0,%1,%2,%3}, [%4];"
                 : "=r"(r[0]), "=r"(r[1]), "=r"(r[2]), "=r"(r[3]) : "r"(addr));
}
__device__ __forceinline__ void ldsm4t(unsigned* r, unsigned addr) {
    asm volatile("ldmatrix.sync.aligned.m8n8.x4.trans.shared.b16 {%0,%1,%2,%3}, [%4];"
                 : "=r"(r[0]), "=r"(r[1]), "=r"(r[2]), "=r"(r[3]) : "r"(addr));
}
__device__ __forceinline__ void mma_bf16(float* c, const unsigned* a, const unsigned* b) {
    asm volatile("mma.sync.aligned.m16n8k16.row.col.f32.bf16.bf16.f32 "
                 "{%0,%1,%2,%3},{%4,%5,%6,%7},{%8,%9},{%0,%1,%2,%3};"
                 : "+f"(c[0]), "+f"(c[1]), "+f"(c[2]), "+f"(c[3])
                 : "r"(a[0]), "r"(a[1]), "r"(a[2]), "r"(a[3]), "r"(b[0]), "r"(b[1]));
}
__device__ __forceinline__ int swz(int row, int chunk) {
    return row * 64 + ((chunk ^ ((row >> 1) & 3)) << 4);
}
__device__ __forceinline__ unsigned packbf(float x, float y) {
    __nv_bfloat162 t = __floats2bfloat162_rn(x, y);
    return *reinterpret_cast<unsigned*>(&t);
}
__device__ __forceinline__ float gelu_exact(float x) {
    return 0.5f * x * (1.0f + erff(x * 0.70710678118654752440f));
}

// ---- fused weight convert+transpose ----
#define WC1 110592
#define WC2 (WC1 + 36864)
#define WC3 (WC2 + 147456)
#define WC4 (WC3 + 147456)
__global__ void wconv_all(const float* __restrict__ qkv_w, const float* __restrict__ proj_w,
                          const float* __restrict__ w1, const float* __restrict__ w2) {
    int idx = blockIdx.x * 256 + threadIdx.x;
    if (idx < WC1) {
        int k = idx / 576, n = idx - k * 576;
        g_qkvw_t[n * 192 + k] = __float2bfloat16_rn(qkv_w[idx]);
    } else if (idx < WC2) {
        int i = idx - WC1; int k = i / 192, n = i - k * 192;
        g_projw_t[n * 192 + k] = __float2bfloat16_rn(proj_w[i]);
    } else if (idx < WC3) {
        int i = idx - WC2; int k = i / 768, n = i - k * 768;
        g_w1_t[n * 192 + k] = __float2bfloat16_rn(w1[i]);
    } else if (idx < WC4) {
        int i = idx - WC3; int k = i / 192, n = i - k * 192;
        g_w2_t[n * 768 + k] = __float2bfloat16_rn(w2[i]);
    }
}

// ---- LayerNorm fp32 -> bf16 (LN1 only) ----
template <bool GATHER>
__global__ void ln_kernel(const float* __restrict__ in, __nv_bfloat16* __restrict__ out,
                          const float* __restrict__ gamma, const float* __restrict__ beta) {
    int warp = (blockIdx.x * blockDim.x + threadIdx.x) >> 5;
    int lane = threadIdx.x & 31;
    if (warp >= TOKENS) return;
    int src = GATHER ? win_to_tok(warp) : warp;
    const float* row = in + (size_t)src * CDIM;

    float v[6];
    float mu = 0.f;
#pragma unroll
    for (int i = 0; i < 6; i++) { v[i] = row[lane + 32 * i]; mu += v[i]; }
#pragma unroll
    for (int o = 16; o; o >>= 1) mu += __shfl_xor_sync(0xffffffffu, mu, o);
    mu *= (1.f / 192.f);
    float var = 0.f;
#pragma unroll
    for (int i = 0; i < 6; i++) { float d = v[i] - mu; var += d * d; }
#pragma unroll
    for (int o = 16; o; o >>= 1) var += __shfl_xor_sync(0xffffffffu, var, o);
    var *= (1.f / 192.f);
    float rstd = rsqrtf(var + 1e-5f);

    __nv_bfloat16* orow = out + (size_t)warp * CDIM;
#pragma unroll
    for (int i = 0; i < 6; i++) {
        int c = lane + 32 * i;
        orow[c] = __float2bfloat16_rn((v[i] - mu) * rstd * gamma[c] + beta[c]);
    }
}

// ====== fused QKV GEMM + attention + proj (+scatter+residual) + LN2 ======
#define FQ_SMA   0
#define FQ_SMB   49152
#define FQ_OUT   65536
#define FQ_BIAS  212992
#define FQ_TOTAL 218496

__global__ void __launch_bounds__(256) qkv_attn_proj(
        const __nv_bfloat16* __restrict__ A,    // winln [TOKENS,192]
        const __nv_bfloat16* __restrict__ Bt,   // qkvw_t [576,192]
        const float* __restrict__ bias,         // qkv_b
        const float* __restrict__ rpb,          // [225,6]
        const __nv_bfloat16* __restrict__ Pt,   // projw_t [192,192]
        const float* __restrict__ pbias,        // proj_b
        const float* __restrict__ xres,         // x fp32 (residual)
        float* __restrict__ x2out,              // x2 fp32
        const float* __restrict__ n2w, const float* __restrict__ n2b,
        __nv_bfloat16* __restrict__ h2out) {    // h2 bf16
    extern __shared__ __align__(16) unsigned char dsm[];
    const unsigned sb = scvta(dsm);
    const int m0 = blockIdx.x * 128;
    const int tid = threadIdx.x;
    const int lane = tid & 31;
    const int wid = tid >> 5;
    const int mw = wid & 3, nw = wid >> 2;

    // ---- A load ----
    {
        const int row = tid >> 1;
        const int c0 = (tid & 1) * 12;
        const __nv_bfloat16* ar = A + (size_t)(m0 + row) * 192 + c0 * 8;
#pragma unroll
        for (int j = 0; j < 12; j++) {
            int c = c0 + j;
            cp16s(sb + FQ_SMA + (c >> 2) * 8192 + swz(row, c & 3), ar + j * 8);
        }
        cp_commit();
    }
    for (int i = tid; i < 1350; i += 256)
        *(float*)(dsm + FQ_BIAS + i * 4) = rpb[i];

    const int brow = tid >> 2, bch = tid & 3;
#pragma unroll
    for (int p = 0; p < 3; p++) {
        cp16s(sb + FQ_SMB + p * 4096 + swz(brow, bch),
              Bt + (size_t)brow * 192 + p * 32 + bch * 8);
        cp_commit();
    }

    const int rowA0 = mw * 32 + (lane & 7) + ((lane >> 3) & 1) * 8;
    const int cHalfA = lane >> 4;
    const int rowB0 = nw * 32 + ((lane >> 4) << 3) + (lane & 7);
    const int cHalfB = (lane >> 3) & 1;

    // ================= phase 1: QKV GEMM =================
    {
        int pn = 0, pk = 3, pmod = 3, cmod = 0;
        for (int nc = 0; nc < 9; nc++) {
            float acc[2][4][4];
#pragma unroll
            for (int i = 0; i < 2; i++)
#pragma unroll
                for (int j = 0; j < 4; j++)
#pragma unroll
                    for (int l = 0; l < 4; l++) acc[i][j][l] = 0.f;

#pragma unroll
            for (int k = 0; k < 6; k++) {
                cp_wait<2>();
                __syncthreads();
                if (pn < 9) {
                    cp16s(sb + FQ_SMB + pmod * 4096 + swz(brow, bch),
                          Bt + (size_t)(pn * 64 + brow) * 192 + pk * 32 + bch * 8);
                }
                cp_commit();
                pmod = (pmod + 1) & 3;
                if (++pk == 6) { pk = 0; pn++; }

                const unsigned As_u = sb + FQ_SMA + k * 8192;
                const unsigned Bs_u = sb + FQ_SMB + cmod * 4096;
                cmod = (cmod + 1) & 3;
#pragma unroll
                for (int s = 0; s < 2; s++) {
                    unsigned af[2][4], bf[2][4];
                    const int chA = 2 * s + cHalfA;
                    const int chB = 2 * s + cHalfB;
#pragma unroll
                    for (int t = 0; t < 2; t++) {
                        int row = rowA0 + t * 16;
                        ldsm4(af[t], As_u + row * 64 + ((chA ^ ((row >> 1) & 3)) << 4));
                    }
#pragma unroll
                    for (int t = 0; t < 2; t++) {
                        int row = rowB0 + t * 16;
                        ldsm4(bf[t], Bs_u + row * 64 + ((chB ^ ((row >> 1) & 3)) << 4));
                    }
#pragma unroll
                    for (int mt = 0; mt < 2; mt++)
#pragma unroll
                        for (int nt = 0; nt < 4; nt++)
                            mma_bf16(acc[mt][nt], af[mt], &bf[nt >> 1][(nt & 1) * 2]);
                }
            }

            const int t3 = nc / 3;
            const int cw0 = (nc - t3 * 3) * 64;
#pragma unroll
            for (int mt = 0; mt < 2; mt++) {
#pragma unroll
                for (int nt = 0; nt < 4; nt++) {
                    const int col = cw0 + nw * 32 + nt * 8 + (lane & 3) * 2;
                    const int head = col >> 5, d = col & 31;
                    const int gcol = nc * 64 + nw * 32 + nt * 8 + (lane & 3) * 2;
                    const float bx = bias[gcol], by = bias[gcol + 1];
                    const int rbase = mw * 32 + mt * 16 + (lane >> 2);
                    const unsigned obase = sb + FQ_OUT + t3 * 49152 + head * 8192;
#pragma unroll
                    for (int half = 0; half < 2; half++) {
                        const int r = rbase + half * 8;
                        unsigned pkd = packbf(acc[mt][nt][half * 2] + bx,
                                              acc[mt][nt][half * 2 + 1] + by);
                        asm volatile("st.shared.b32 [%0], %1;"
                                     :: "r"(obase + swz(r, d >> 3) + (d & 7) * 2), "r"(pkd)
                                     : "memory");
                    }
                }
            }
        }
    }
    __syncthreads();

    // ================= phase 2: attention (O -> Q smem region) =================
    const int win = wid >> 2;
    const int lwid = wid & 3;
    const int w = blockIdx.x * 2 + win;
    const int wi = (w >> 4) & 15, wj = w & 15;
    const int wro = win * 64;
    const unsigned qb = sb + FQ_OUT;
    const unsigned kb = qb + 49152;
    const unsigned vb = kb + 49152;
    const float scale = 0.1767766952966368811f;

    const int rowOffA = (lane & 7) + ((lane >> 3) & 1) * 8;
    const int cHA = lane >> 4;
    const int rowOffB = ((lane >> 4) << 3) + (lane & 7);
    const int cHB = (lane >> 3) & 1;

    const int r0 = lwid * 16 + (lane >> 2);
    const int r1 = r0 + 8;
    const int rn0 = r0 >> 3, cn0 = r0 & 7;
    const int rn1 = r1 >> 3, cn1 = r1 & 7;
    const int li = (wi == 15), lj = (wj == 15);
    const int lab0 = (li ? (rn0 < 4 ? 1 : 2) : 0) * 3 + (lj ? (cn0 < 4 ? 1 : 2) : 0);
    const int lab1 = (li ? (rn1 < 4 ? 1 : 2) : 0) * 3 + (lj ? (cn1 < 4 ? 1 : 2) : 0);

    for (int h = 0; h < NHEADS; h++) {
        const unsigned qh = qb + h * 8192, kh = kb + h * 8192, vh = vb + h * 8192;

        float sacc[8][4];
#pragma unroll
        for (int i = 0; i < 8; i++)
#pragma unroll
            for (int j = 0; j < 4; j++) sacc[i][j] = 0.f;

#pragma unroll
        for (int kk = 0; kk < 2; kk++) {
            unsigned aq[4];
            {
                int row = wro + lwid * 16 + rowOffA;
                int ch = kk * 2 + cHA;
                ldsm4(aq, qh + row * 64 + ((ch ^ ((row >> 1) & 3)) << 4));
            }
#pragma unroll
            for (int nt2 = 0; nt2 < 4; nt2++) {
                unsigned bk[4];
                int row = wro + nt2 * 16 + rowOffB;
                int ch = kk * 2 + cHB;
                ldsm4(bk, kh + row * 64 + ((ch ^ ((row >> 1) & 3)) << 4));
                mma_bf16(sacc[nt2 * 2 + 0], aq, &bk[0]);
                mma_bf16(sacc[nt2 * 2 + 1], aq, &bk[2]);
            }
        }

#pragma unroll
        for (int nt = 0; nt < 8; nt++) {
#pragma unroll
            for (int j = 0; j < 4; j++) {
                int m = nt * 8 + (lane & 3) * 2 + (j & 1);
                int rm = m >> 3, cm = m & 7;
                int labm = (li ? (rm < 4 ? 1 : 2) : 0) * 3 + (lj ? (cm < 4 ? 1 : 2) : 0);
                float v = sacc[nt][j] * scale;
                int idx;
                if (j < 2) {
                    idx = (rn0 - rm + 7) * 15 + (cn0 - cm + 7);
                    v += *(float*)(dsm + FQ_BIAS + (idx * 6 + h) * 4);
                    if (labm != lab0) v -= 100.f;
                } else {
                    idx = (rn1 - rm + 7) * 15 + (cn1 - cm + 7);
                    v += *(float*)(dsm + FQ_BIAS + (idx * 6 + h) * 4);
                    if (labm != lab1) v -= 100.f;
                }
                sacc[nt][j] = v;
            }
        }

        float mx0 = -1e30f, mx1 = -1e30f;
#pragma unroll
        for (int nt = 0; nt < 8; nt++) {
            mx0 = fmaxf(mx0, fmaxf(sacc[nt][0], sacc[nt][1]));
            mx1 = fmaxf(mx1, fmaxf(sacc[nt][2], sacc[nt][3]));
        }
        mx0 = fmaxf(mx0, __shfl_xor_sync(0xffffffffu, mx0, 1));
        mx0 = fmaxf(mx0, __shfl_xor_sync(0xffffffffu, mx0, 2));
        mx1 = fmaxf(mx1, __shfl_xor_sync(0xffffffffu, mx1, 1));
        mx1 = fmaxf(mx1, __shfl_xor_sync(0xffffffffu, mx1, 2));
        float sum0 = 0.f, sum1 = 0.f;
#pragma unroll
        for (int nt = 0; nt < 8; nt++) {
            sacc[nt][0] = __expf(sacc[nt][0] - mx0); sum0 += sacc[nt][0];
            sacc[nt][1] = __expf(sacc[nt][1] - mx0); sum0 += sacc[nt][1];
            sacc[nt][2] = __expf(sacc[nt][2] - mx1); sum1 += sacc[nt][2];
            sacc[nt][3] = __expf(sacc[nt][3] - mx1); sum1 += sacc[nt][3];
        }
        sum0 += __shfl_xor_sync(0xffffffffu, sum0, 1);
        sum0 += __shfl_xor_sync(0xffffffffu, sum0, 2);
        sum1 += __shfl_xor_sync(0xffffffffu, sum1, 1);
        sum1 += __shfl_xor_sync(0xffffffffu, sum1, 2);
        const float inv0 = 1.f / sum0, inv1 = 1.f / sum1;

        float oacc[4][4];
#pragma unroll
        for (int i = 0; i < 4; i++)
#pragma unroll
            for (int j = 0; j < 4; j++) oacc[i][j] = 0.f;

#pragma unroll
        for (int kk2 = 0; kk2 < 4; kk2++) {
            unsigned ap[4];
            ap[0] = packbf(sacc[2 * kk2][0], sacc[2 * kk2][1]);
            ap[1] = packbf(sacc[2 * kk2][2], sacc[2 * kk2][3]);
            ap[2] = packbf(sacc[2 * kk2 + 1][0], sacc[2 * kk2 + 1][1]);
            ap[3] = packbf(sacc[2 * kk2 + 1][2], sacc[2 * kk2 + 1][3]);
#pragma unroll
            for (int nt2 = 0; nt2 < 2; nt2++) {
                unsigned bv[4];
                int row = wro + kk2 * 16 + (lane & 7) + ((lane >> 3) & 1) * 8;
                int ch = 2 * nt2 + (lane >> 4);
                ldsm4t(bv, vh + row * 64 + ((ch ^ ((row >> 1) & 3)) << 4));
                mma_bf16(oacc[nt2 * 2 + 0], ap, &bv[0]);
                mma_bf16(oacc[nt2 * 2 + 1], ap, &bv[2]);
            }
        }

        const int grow0 = wro + r0;
        const int grow1 = wro + r1;
        const int d0 = (lane & 3) * 2;
#pragma unroll
        for (int nt = 0; nt < 4; nt++) {
            const int d = nt * 8 + d0;
            unsigned p0 = packbf(oacc[nt][0] * inv0, oacc[nt][1] * inv0);
            unsigned p1 = packbf(oacc[nt][2] * inv1, oacc[nt][3] * inv1);
            asm volatile("st.shared.b32 [%0], %1;"
                         :: "r"(qh + swz(grow0, d >> 3) + (d & 7) * 2), "r"(p0) : "memory");
            asm volatile("st.shared.b32 [%0], %1;"
                         :: "r"(qh + swz(grow1, d >> 3) + (d & 7) * 2), "r"(p1) : "memory");
        }
    }
    cp_wait<0>();
    __syncthreads();

    // ================= phase 3: proj GEMM, scatter + residual -> x2 =================
    {
#pragma unroll
        for (int p = 0; p < 3; p++) {
            cp16s(sb + FQ_SMB + p * 4096 + swz(brow, bch),
                  Pt + (size_t)brow * 192 + p * 32 + bch * 8);
            cp_commit();
        }
        int pn = 0, pk = 3, pmod = 3, cmod = 0;
        for (int nc = 0; nc < 3; nc++) {
            float acc[2][4][4];
#pragma unroll
            for (int i = 0; i < 2; i++)
#pragma unroll
                for (int j = 0; j < 4; j++)
#pragma unroll
                    for (int l = 0; l < 4; l++) acc[i][j][l] = 0.f;

#pragma unroll
            for (int k = 0; k < 6; k++) {
                cp_wait<2>();
                __syncthreads();
                if (pn < 3) {
                    cp16s(sb + FQ_SMB + pmod * 4096 + swz(brow, bch),
                          Pt + (size_t)(pn * 64 + brow) * 192 + pk * 32 + bch * 8);
                }
                cp_commit();
                pmod = (pmod + 1) & 3;
                if (++pk == 6) { pk = 0; pn++; }

                const unsigned As_u = qb + k * 8192;
                const unsigned Bs_u = sb + FQ_SMB + cmod * 4096;
                cmod = (cmod + 1) & 3;
#pragma unroll
                for (int s = 0; s < 2; s++) {
                    unsigned af[2][4], bf[2][4];
                    const int chA = 2 * s + cHalfA;
                    const int chB = 2 * s + cHalfB;
#pragma unroll
                    for (int t = 0; t < 2; t++) {
                        int row = rowA0 + t * 16;
                        ldsm4(af[t], As_u + row * 64 + ((chA ^ ((row >> 1) & 3)) << 4));
                    }
#pragma unroll
                    for (int t = 0; t < 2; t++) {
                        int row = rowB0 + t * 16;
                        ldsm4(bf[t], Bs_u + row * 64 + ((chB ^ ((row >> 1) & 3)) << 4));
                    }
#pragma unroll
                    for (int mt = 0; mt < 2; mt++)
#pragma unroll
                        for (int nt = 0; nt < 4; nt++)
                            mma_bf16(acc[mt][nt], af[mt], &bf[nt >> 1][(nt & 1) * 2]);
                }
            }

#pragma unroll
            for (int mt = 0; mt < 2; mt++) {
#pragma unroll
                for (int nt = 0; nt < 4; nt++) {
                    const float* c = acc[mt][nt];
                    const int col = nc * 64 + nw * 32 + nt * 8 + (lane & 3) * 2;
                    const float bx = pbias[col], by = pbias[col + 1];
                    const int rbase = mw * 32 + mt * 16 + (lane >> 2);
#pragma unroll
                    for (int half = 0; half < 2; half++) {
                        int m = rbase + half * 8;
                        int dst = win_to_tok(m0 + m);
                        size_t idx = (size_t)dst * CDIM + col;
                        float2 res = *(const float2*)&xres[idx];
                        *(float2*)&x2out[idx] = make_float2(c[half * 2] + bx + res.x,
                                                            c[half * 2 + 1] + by + res.y);
                    }
                }
            }
        }
    }
    __syncthreads();   // block-wide visibility of this block's x2 writes

    // ================= phase 4: LN2 on this block's 128 rows (x2 from L2) =================
    {
        const int row = tid >> 1, hf = tid & 1;
        const int tok = win_to_tok(m0 + row);
        const float4* xr = (const float4*)(x2out + (size_t)tok * 192) + hf * 24;
        float sum = 0.f, sq = 0.f;
#pragma unroll
        for (int j = 0; j < 24; j++) {
            float4 v = xr[j];
            sum += v.x + v.y + v.z + v.w;
            sq += v.x * v.x + v.y * v.y + v.z * v.z + v.w * v.w;
        }
        sum += __shfl_xor_sync(0xffffffffu, sum, 1);
        sq  += __shfl_xor_sync(0xffffffffu, sq, 1);
        float mu = sum * (1.f / 192.f);
        float var = sq * (1.f / 192.f) - mu * mu;
        float rstd = rsqrtf(var + 1e-5f);

        __nv_bfloat16* hr = h2out + (size_t)tok * 192 + hf * 96;
#pragma unroll
        for (int j = 0; j < 24; j++) {
            float4 v = xr[j];
            int f = hf * 24 + j;
            float4 g = ((const float4*)n2w)[f];
            float4 b = ((const float4*)n2b)[f];
            uint2 p;
            p.x = packbf((v.x - mu) * rstd * g.x + b.x, (v.y - mu) * rstd * g.y + b.y);
            p.y = packbf((v.z - mu) * rstd * g.z + b.z, (v.w - mu) * rstd * g.w + b.w);
            *(uint2*)(hr + j * 4) = p;
        }
    }
}

// ---- mma.sync bf16 GEMM 128x64 (MLP2), 3-stage pipeline ----
#define BUFSZ ((128 + 64) * 64)
template <int EPI, int NSTEPS, typename OutT>
__global__ void __launch_bounds__(256) gemm_bf16(
        const __nv_bfloat16* __restrict__ A, const __nv_bfloat16* __restrict__ Bt,
        const float* __restrict__ bias, OutT* __restrict__ C,
        const float* __restrict__ R, int N) {
    __shared__ __align__(16) unsigned char smem[3 * BUFSZ];
    const int K = NSTEPS * 32;

    const int m0 = blockIdx.y * 128;
    const int n0 = blockIdx.x * 64;
    const int tid = threadIdx.x;
    const int lane = tid & 31;
    const int wid = tid >> 5;
    const int mw = wid & 3;
    const int nw = wid >> 2;

    const int a_row = tid >> 1;
    const int a_c0 = (tid & 1) * 2;
    const int b_row = tid >> 2;
    const int b_c = tid & 3;
    const __nv_bfloat16* aptr = A + (size_t)(m0 + a_row) * K + a_c0 * 8;
    const __nv_bfloat16* bptr = Bt + (size_t)(n0 + b_row) * K + b_c * 8;
    const int sA0 = swz(a_row, a_c0), sA1 = swz(a_row, a_c0 + 1), sB = swz(b_row, b_c);

    float acc[2][4][4];
#pragma unroll
    for (int i = 0; i < 2; i++)
#pragma unroll
        for (int j = 0; j < 4; j++)
#pragma unroll
            for (int l = 0; l < 4; l++) acc[i][j][l] = 0.f;

    const int rowA0 = mw * 32 + (lane & 7) + ((lane >> 3) & 1) * 8;
    const int cHalfA = lane >> 4;
    const int rowB0 = nw * 32 + ((lane >> 4) << 3) + (lane & 7);
    const int cHalfB = (lane >> 3) & 1;

#pragma unroll
    for (int p = 0; p < 2; p++) {
        unsigned char* As = smem + p * BUFSZ;
        unsigned char* Bs = As + 128 * 64;
        cp16(As + sA0, aptr + p * 32);
        cp16(As + sA1, aptr + p * 32 + 8);
        cp16(Bs + sB, bptr + p * 32);
        cp_commit();
    }

#pragma unroll
    for (int step = 0; step < NSTEPS; step++) {
        if (step == NSTEPS - 1) cp_wait<0>(); else cp_wait<1>();
        __syncthreads();

        if (step + 2 < NSTEPS) {
            unsigned char* As = smem + ((step + 2) % 3) * BUFSZ;
            unsigned char* Bs = As + 128 * 64;
            cp16(As + sA0, aptr + (step + 2) * 32);
            cp16(As + sA1, aptr + (step + 2) * 32 + 8);
            cp16(Bs + sB, bptr + (step + 2) * 32);
            cp_commit();
        }

        const unsigned As_u = scvta(smem + (step % 3) * BUFSZ);
        const unsigned Bs_u = As_u + 128 * 64;
#pragma unroll
        for (int s = 0; s < 2; s++) {
            unsigned af[2][4], bf[2][4];
            const int chA = 2 * s + cHalfA;
            const int chB = 2 * s + cHalfB;
#pragma unroll
            for (int t = 0; t < 2; t++) {
                int row = rowA0 + t * 16;
                ldsm4(af[t], As_u + row * 64 + ((chA ^ ((row >> 1) & 3)) << 4));
            }
#pragma unroll
            for (int t = 0; t < 2; t++) {
                int row = rowB0 + t * 16;
                ldsm4(bf[t], Bs_u + row * 64 + ((chB ^ ((row >> 1) & 3)) << 4));
            }
#pragma unroll
            for (int mt = 0; mt < 2; mt++)
#pragma unroll
                for (int nt = 0; nt < 4; nt++)
                    mma_bf16(acc[mt][nt], af[mt], &bf[nt >> 1][(nt & 1) * 2]);
        }
    }

#pragma unroll
    for (int mt = 0; mt < 2; mt++) {
#pragma unroll
        for (int nt = 0; nt < 4; nt++) {
            const float* c = acc[mt][nt];
            const int col = n0 + nw * 32 + nt * 8 + (lane & 3) * 2;
            const float bx = bias[col], by = bias[col + 1];
            const int rbase = m0 + mw * 32 + mt * 16 + (lane >> 2);
#pragma unroll
            for (int half = 0; half < 2; half++) {
                int m = rbase + half * 8;
                float vx = c[half * 2 + 0] + bx;
                float vy = c[half * 2 + 1] + by;
                if (EPI == 1) { vx = gelu_exact(vx); vy = gelu_exact(vy); }
                if (EPI == 3) {
                    size_t idx = (size_t)m * N + col;
                    float2 res = *(const float2*)&R[idx];
                    *(float2*)((float*)C + idx) = make_float2(vx + res.x, vy + res.y);
                } else {
                    __nv_bfloat162 o = __floats2bfloat162_rn(vx, vy);
                    *(__nv_bfloat162*)((__nv_bfloat16*)C + (size_t)m * N + col) = o;
                }
            }
        }
    }
}

// ---- wide bf16 GEMM 128x128x32 (MLP1: K=192, GELU, bf16 out) ----
#define WBUF (256 * 64)
__global__ void __launch_bounds__(256) gemm_wide_gelu(
        const __nv_bfloat16* __restrict__ A, const __nv_bfloat16* __restrict__ Bt,
        const float* __restrict__ bias, __nv_bfloat16* __restrict__ C, int N) {
    __shared__ __align__(16) unsigned char smem[3 * WBUF];
    const int K = 192, NSTEPS = 6;

    const int m0 = blockIdx.y * 128;
    const int n0 = blockIdx.x * 128;
    const int tid = threadIdx.x;
    const int lane = tid & 31;
    const int wid = tid >> 5;
    const int mw = wid & 3;
    const int nw = wid >> 2;

    const int l_row = tid >> 1;
    const int l_c0 = (tid & 1) * 2;
    const __nv_bfloat16* aptr = A + (size_t)(m0 + l_row) * K + l_c0 * 8;
    const __nv_bfloat16* bptr = Bt + (size_t)(n0 + l_row) * K + l_c0 * 8;
    const int sL0 = swz(l_row, l_c0), sL1 = swz(l_row, l_c0 + 1);

    float acc[2][8][4];
#pragma unroll
    for (int i = 0; i < 2; i++)
#pragma unroll
        for (int j = 0; j < 8; j++)
#pragma unroll
            for (int l = 0; l < 4; l++) acc[i][j][l] = 0.f;

    const int rowA0 = mw * 32 + (lane & 7) + ((lane >> 3) & 1) * 8;
    const int cHalfA = lane >> 4;
    const int rowB0 = nw * 64 + ((lane >> 4) << 3) + (lane & 7);
    const int cHalfB = (lane >> 3) & 1;

#pragma unroll
    for (int p = 0; p < 2; p++) {
        unsigned char* As = smem + p * WBUF;
        unsigned char* Bs = As + 128 * 64;
        cp16(As + sL0, aptr + p * 32);
        cp16(As + sL1, aptr + p * 32 + 8);
        cp16(Bs + sL0, bptr + p * 32);
        cp16(Bs + sL1, bptr + p * 32 + 8);
        cp_commit();
    }

#pragma unroll
    for (int step = 0; step < NSTEPS; step++) {
        if (step == NSTEPS - 1) cp_wait<0>(); else cp_wait<1>();
        __syncthreads();

        if (step + 2 < NSTEPS) {
            unsigned char* As = smem + ((step + 2) % 3) * WBUF;
            unsigned char* Bs = As + 128 * 64;
            cp16(As + sL0, aptr + (step + 2) * 32);
            cp16(As + sL1, aptr + (step + 2) * 32 + 8);
            cp16(Bs + sL0, bptr + (step + 2) * 32);
            cp16(Bs + sL1, bptr + (step + 2) * 32 + 8);
            cp_commit();
        }

        const unsigned As_u = scvta(smem + (step % 3) * WBUF);
        const unsigned Bs_u = As_u + 128 * 64;
#pragma unroll
        for (int s = 0; s < 2; s++) {
            unsigned af[2][4], bf[4][4];
            const int chA = 2 * s + cHalfA;
            const int chB = 2 * s + cHalfB;
#pragma unroll
            for (int t = 0; t < 2; t++) {
                int row = rowA0 + t * 16;
                ldsm4(af[t], As_u + row * 64 + ((chA ^ ((row >> 1) & 3)) << 4));
            }
#pragma unroll
            for (int t = 0; t < 4; t++) {
                int row = rowB0 + t * 16;
                ldsm4(bf[t], Bs_u + row * 64 + ((chB ^ ((row >> 1) & 3)) << 4));
            }
#pragma unroll
            for (int mt = 0; mt < 2; mt++)
#pragma unroll
                for (int nt = 0; nt < 8; nt++)
                    mma_bf16(acc[mt][nt], af[mt], &bf[nt >> 1][(nt & 1) * 2]);
        }
    }

#pragma unroll
    for (int mt = 0; mt < 2; mt++) {
#pragma unroll
        for (int nt = 0; nt < 8; nt++) {
            const float* c = acc[mt][nt];
            const int col = n0 + nw * 64 + nt * 8 + (lane & 3) * 2;
            const float bx = bias[col], by = bias[col + 1];
            const int rbase = m0 + mw * 32 + mt * 16 + (lane >> 2);
#pragma unroll
            for (int half = 0; half < 2; half++) {
                int m = rbase + half * 8;
                float vx = gelu_exact(c[half * 2 + 0] + bx);
                float vy = gelu_exact(c[half * 2 + 1] + by);
                *(unsigned*)(C + (size_t)m * N + col) = packbf(vx, vy);
            }
        }
    }
}

// -------------------- launch --------------------
extern "C" void kernel_launch(void* const* d_in, const int* in_sizes, int n_in,
                              void* d_out, int out_size) {
    (void)in_sizes; (void)n_in; (void)out_size;
    const float* x      = (const float*)d_in[0];
    const float* qkv_w  = (const float*)d_in[3];
    const float* qkv_b  = (const float*)d_in[4];
    const float* proj_w = (const float*)d_in[5];
    const float* proj_b = (const float*)d_in[6];
    const float* rpb    = (const float*)d_in[7];
    const float* n1w    = (const float*)d_in[8];
    const float* n1b    = (const float*)d_in[9];
    const float* n2w    = (const float*)d_in[10];
    const float* n2b    = (const float*)d_in[11];
    const float* w1     = (const float*)d_in[12];
    const float* b1     = (const float*)d_in[13];
    const float* w2     = (const float*)d_in[14];
    const float* b2     = (const float*)d_in[15];
    float* out = (float*)d_out;

    __nv_bfloat16 *winln, *h2, *mlpg;
    __nv_bfloat16 *qkvw_t, *projw_t, *w1_t, *w2_t;
    float* x2;
    cudaGetSymbolAddress((void**)&winln,  g_winln);
    cudaGetSymbolAddress((void**)&x2,     g_x2);
    cudaGetSymbolAddress((void**)&h2,     g_h2);
    cudaGetSymbolAddress((void**)&mlpg,   g_mlp);
    cudaGetSymbolAddress((void**)&qkvw_t, g_qkvw_t);
    cudaGetSymbolAddress((void**)&projw_t,g_projw_t);
    cudaGetSymbolAddress((void**)&w1_t,   g_w1_t);
    cudaGetSymbolAddress((void**)&w2_t,   g_w2_t);

    static bool attr_set = false;
    if (!attr_set) {
        cudaFuncSetAttribute(qkv_attn_proj, cudaFuncAttributeMaxDynamicSharedMemorySize, FQ_TOTAL);
        attr_set = true;
    }

    wconv_all<<<(WC4 + 255) / 256, 256>>>(qkv_w, proj_w, w1, w2);

    // 1. LN1 + shift + window gather (fp32 -> bf16)
    ln_kernel<true><<<TOKENS / 8, 256>>>(x, winln, n1w, n1b);
    // 2. fused QKV GEMM + attention + proj + residual + LN2 -> x2 fp32, h2 bf16
    qkv_attn_proj<<<NWIN / 2, 256, FQ_TOTAL>>>(winln, qkvw_t, qkv_b, rpb,
                                               projw_t, proj_b, x, x2, n2w, n2b, h2);
    // 3. MLP1 + GELU -> bf16 (wide 128x128 tiles)
    gemm_wide_gelu<<<dim3(6, TOKENS / 128), 256>>>(h2, w1_t, b1, mlpg, HIDDEN);
    // 4. MLP2 + residual -> fp32 out
    gemm_bf16<3, 24, float><<<dim3(3, TOKENS / 128), 256>>>(
        mlpg, w2_t, b2, out, x2, CDIM);
}

// round 16
// speedup vs baseline: 1.1065x; 1.1065x over previous
#include <cuda_runtime.h>
#include <cuda_bf16.h>
#include <math.h>
#include <stdint.h>

#define TOKENS   131072
#define CDIM     192
#define NHEADS   6
#define HD       32
#define NWIN     2048
#define HIDDEN   768

// ---- scratch ----
__device__ __align__(16) __nv_bfloat16 g_winln[TOKENS * CDIM];
__device__ __align__(16) float         g_x2   [TOKENS * CDIM];
__device__ __align__(16) __nv_bfloat16 g_h2   [TOKENS * CDIM];
__device__ __align__(16) __nv_bfloat16 g_mlp  [TOKENS * HIDDEN];
__device__ __align__(16) __nv_bfloat16 g_qkvw_t[3 * CDIM * CDIM];
__device__ __align__(16) __nv_bfloat16 g_projw_t[CDIM * CDIM];
__device__ __align__(16) __nv_bfloat16 g_w1_t[HIDDEN * CDIM];
__device__ __align__(16) __nv_bfloat16 g_w2_t[CDIM * HIDDEN];

__device__ __forceinline__ int win_to_tok(int t) {
    int w = t >> 6, n = t & 63;
    int b  = w >> 8;
    int wi = (w >> 4) & 15;
    int wj = w & 15;
    int r = n >> 3, c = n & 7;
    int row = (wi * 8 + r + 4) & 127;
    int col = (wj * 8 + c + 4) & 127;
    return (b << 14) + (row << 7) + col;
}

// ---- helpers ----
__device__ __forceinline__ unsigned scvta(const void* p) {
    return (unsigned)__cvta_generic_to_shared(p);
}
__device__ __forceinline__ void cp16(void* dst, const void* src) {
    asm volatile("cp.async.cg.shared.global [%0], [%1], 16;" :: "r"(scvta(dst)), "l"(src));
}
__device__ __forceinline__ void cp16s(unsigned dst, const void* src) {
    asm volatile("cp.async.cg.shared.global [%0], [%1], 16;" :: "r"(dst), "l"(src));
}
__device__ __forceinline__ void cp_commit() { asm volatile("cp.async.commit_group;"); }
template <int N>
__device__ __forceinline__ void cp_wait() { asm volatile("cp.async.wait_group %0;" :: "n"(N)); }

__device__ __forceinline__ void ldsm4(unsigned* r, unsigned addr) {
    asm volatile("ldmatrix.sync.aligned.m8n8.x4.shared.b16 {%0,%1,%2,%3}, [%4];"
                 : "=r"(r[0]), "=r"(r[1]), "=r"(r[2]), "=r"(r[3]) : "r"(addr));
}
__device__ __forceinline__ void ldsm4t(unsigned* r, unsigned addr) {
    asm volatile("ldmatrix.sync.aligned.m8n8.x4.trans.shared.b16 {%0,%1,%2,%3}, [%4];"
                 : "=r"(r[0]), "=r"(r[1]), "=r"(r[2]), "=r"(r[3]) : "r"(addr));
}
__device__ __forceinline__ void mma_bf16(float* c, const unsigned* a, const unsigned* b) {
    asm volatile("mma.sync.aligned.m16n8k16.row.col.f32.bf16.bf16.f32 "
                 "{%0,%1,%2,%3},{%4,%5,%6,%7},{%8,%9},{%0,%1,%2,%3};"
                 : "+f"(c[0]), "+f"(c[1]), "+f"(c[2]), "+f"(c[3])
                 : "r"(a[0]), "r"(a[1]), "r"(a[2]), "r"(a[3]), "r"(b[0]), "r"(b[1]));
}
__device__ __forceinline__ int swz(int row, int chunk) {
    return row * 64 + ((chunk ^ ((row >> 1) & 3)) << 4);
}
__device__ __forceinline__ unsigned packbf(float x, float y) {
    __nv_bfloat162 t = __floats2bfloat162_rn(x, y);
    return *reinterpret_cast<unsigned*>(&t);
}
// fast exact-GELU: Abramowitz-Stegun 7.1.26 erf (max abs err 1.5e-7, << bf16 rounding)
__device__ __forceinline__ float gelu_fast(float x) {
    float ax = fabsf(x) * 0.70710678118654752440f;
    float t = __fdividef(1.f, fmaf(0.3275911f, ax, 1.f));
    float poly = t * fmaf(t, fmaf(t, fmaf(t, fmaf(t, 1.061405429f, -1.453152027f),
                                          1.421413741f), -0.284496736f), 0.254829592f);
    float erfabs = 1.f - poly * __expf(-ax * ax);
    float erfv = copysignf(erfabs, x);
    return 0.5f * x * (1.f + erfv);
}

// ---- fused weight convert+transpose ----
#define WC1 110592
#define WC2 (WC1 + 36864)
#define WC3 (WC2 + 147456)
#define WC4 (WC3 + 147456)
__global__ void wconv_all(const float* __restrict__ qkv_w, const float* __restrict__ proj_w,
                          const float* __restrict__ w1, const float* __restrict__ w2) {
    int idx = blockIdx.x * 256 + threadIdx.x;
    if (idx < WC1) {
        int k = idx / 576, n = idx - k * 576;
        g_qkvw_t[n * 192 + k] = __float2bfloat16_rn(qkv_w[idx]);
    } else if (idx < WC2) {
        int i = idx - WC1; int k = i / 192, n = i - k * 192;
        g_projw_t[n * 192 + k] = __float2bfloat16_rn(proj_w[i]);
    } else if (idx < WC3) {
        int i = idx - WC2; int k = i / 768, n = i - k * 768;
        g_w1_t[n * 192 + k] = __float2bfloat16_rn(w1[i]);
    } else if (idx < WC4) {
        int i = idx - WC3; int k = i / 192, n = i - k * 192;
        g_w2_t[n * 768 + k] = __float2bfloat16_rn(w2[i]);
    }
}

// ---- LayerNorm fp32 -> bf16 ----
template <bool GATHER>
__global__ void ln_kernel(const float* __restrict__ in, __nv_bfloat16* __restrict__ out,
                          const float* __restrict__ gamma, const float* __restrict__ beta) {
    int warp = (blockIdx.x * blockDim.x + threadIdx.x) >> 5;
    int lane = threadIdx.x & 31;
    if (warp >= TOKENS) return;
    int src = GATHER ? win_to_tok(warp) : warp;
    const float* row = in + (size_t)src * CDIM;

    float v[6];
    float mu = 0.f;
#pragma unroll
    for (int i = 0; i < 6; i++) { v[i] = row[lane + 32 * i]; mu += v[i]; }
#pragma unroll
    for (int o = 16; o; o >>= 1) mu += __shfl_xor_sync(0xffffffffu, mu, o);
    mu *= (1.f / 192.f);
    float var = 0.f;
#pragma unroll
    for (int i = 0; i < 6; i++) { float d = v[i] - mu; var += d * d; }
#pragma unroll
    for (int o = 16; o; o >>= 1) var += __shfl_xor_sync(0xffffffffu, var, o);
    var *= (1.f / 192.f);
    float rstd = rsqrtf(var + 1e-5f);

    __nv_bfloat16* orow = out + (size_t)warp * CDIM;
#pragma unroll
    for (int i = 0; i < 6; i++) {
        int c = lane + 32 * i;
        orow[c] = __float2bfloat16_rn((v[i] - mu) * rstd * gamma[c] + beta[c]);
    }
}

// ====== fused QKV GEMM + attention + proj (+scatter+residual) ======
#define FQ_SMA   0
#define FQ_SMB   49152
#define FQ_OUT   65536
#define FQ_BIAS  212992
#define FQ_TOTAL 218496

__global__ void __launch_bounds__(256) qkv_attn_proj(
        const __nv_bfloat16* __restrict__ A,
        const __nv_bfloat16* __restrict__ Bt,
        const float* __restrict__ bias,
        const float* __restrict__ rpb,
        const __nv_bfloat16* __restrict__ Pt,
        const float* __restrict__ pbias,
        const float* __restrict__ xres,
        float* __restrict__ x2out) {
    extern __shared__ __align__(16) unsigned char dsm[];
    const unsigned sb = scvta(dsm);
    const int m0 = blockIdx.x * 128;
    const int tid = threadIdx.x;
    const int lane = tid & 31;
    const int wid = tid >> 5;
    const int mw = wid & 3, nw = wid >> 2;

    {
        const int row = tid >> 1;
        const int c0 = (tid & 1) * 12;
        const __nv_bfloat16* ar = A + (size_t)(m0 + row) * 192 + c0 * 8;
#pragma unroll
        for (int j = 0; j < 12; j++) {
            int c = c0 + j;
            cp16s(sb + FQ_SMA + (c >> 2) * 8192 + swz(row, c & 3), ar + j * 8);
        }
        cp_commit();
    }
    for (int i = tid; i < 1350; i += 256)
        *(float*)(dsm + FQ_BIAS + i * 4) = rpb[i];

    const int brow = tid >> 2, bch = tid & 3;
#pragma unroll
    for (int p = 0; p < 3; p++) {
        cp16s(sb + FQ_SMB + p * 4096 + swz(brow, bch),
              Bt + (size_t)brow * 192 + p * 32 + bch * 8);
        cp_commit();
    }

    const int rowA0 = mw * 32 + (lane & 7) + ((lane >> 3) & 1) * 8;
    const int cHalfA = lane >> 4;
    const int rowB0 = nw * 32 + ((lane >> 4) << 3) + (lane & 7);
    const int cHalfB = (lane >> 3) & 1;

    // ---- phase 1: QKV GEMM ----
    {
        int pn = 0, pk = 3, pmod = 3, cmod = 0;
        for (int nc = 0; nc < 9; nc++) {
            float acc[2][4][4];
#pragma unroll
            for (int i = 0; i < 2; i++)
#pragma unroll
                for (int j = 0; j < 4; j++)
#pragma unroll
                    for (int l = 0; l < 4; l++) acc[i][j][l] = 0.f;

#pragma unroll
            for (int k = 0; k < 6; k++) {
                cp_wait<2>();
                __syncthreads();
                if (pn < 9) {
                    cp16s(sb + FQ_SMB + pmod * 4096 + swz(brow, bch),
                          Bt + (size_t)(pn * 64 + brow) * 192 + pk * 32 + bch * 8);
                }
                cp_commit();
                pmod = (pmod + 1) & 3;
                if (++pk == 6) { pk = 0; pn++; }

                const unsigned As_u = sb + FQ_SMA + k * 8192;
                const unsigned Bs_u = sb + FQ_SMB + cmod * 4096;
                cmod = (cmod + 1) & 3;
#pragma unroll
                for (int s = 0; s < 2; s++) {
                    unsigned af[2][4], bf[2][4];
                    const int chA = 2 * s + cHalfA;
                    const int chB = 2 * s + cHalfB;
#pragma unroll
                    for (int t = 0; t < 2; t++) {
                        int row = rowA0 + t * 16;
                        ldsm4(af[t], As_u + row * 64 + ((chA ^ ((row >> 1) & 3)) << 4));
                    }
#pragma unroll
                    for (int t = 0; t < 2; t++) {
                        int row = rowB0 + t * 16;
                        ldsm4(bf[t], Bs_u + row * 64 + ((chB ^ ((row >> 1) & 3)) << 4));
                    }
#pragma unroll
                    for (int mt = 0; mt < 2; mt++)
#pragma unroll
                        for (int nt = 0; nt < 4; nt++)
                            mma_bf16(acc[mt][nt], af[mt], &bf[nt >> 1][(nt & 1) * 2]);
                }
            }

            const int t3 = nc / 3;
            const int cw0 = (nc - t3 * 3) * 64;
#pragma unroll
            for (int mt = 0; mt < 2; mt++) {
#pragma unroll
                for (int nt = 0; nt < 4; nt++) {
                    const int col = cw0 + nw * 32 + nt * 8 + (lane & 3) * 2;
                    const int head = col >> 5, d = col & 31;
                    const int gcol = nc * 64 + nw * 32 + nt * 8 + (lane & 3) * 2;
                    const float bx = bias[gcol], by = bias[gcol + 1];
                    const int rbase = mw * 32 + mt * 16 + (lane >> 2);
                    const unsigned obase = sb + FQ_OUT + t3 * 49152 + head * 8192;
#pragma unroll
                    for (int half = 0; half < 2; half++) {
                        const int r = rbase + half * 8;
                        unsigned pkd = packbf(acc[mt][nt][half * 2] + bx,
                                              acc[mt][nt][half * 2 + 1] + by);
                        asm volatile("st.shared.b32 [%0], %1;"
                                     :: "r"(obase + swz(r, d >> 3) + (d & 7) * 2), "r"(pkd)
                                     : "memory");
                    }
                }
            }
        }
    }
    __syncthreads();

    // ---- phase 2: attention (O -> Q smem region) ----
    const int win = wid >> 2;
    const int lwid = wid & 3;
    const int w = blockIdx.x * 2 + win;
    const int wi = (w >> 4) & 15, wj = w & 15;
    const int wro = win * 64;
    const unsigned qb = sb + FQ_OUT;
    const unsigned kb = qb + 49152;
    const unsigned vb = kb + 49152;
    const float scale = 0.1767766952966368811f;

    const int rowOffA = (lane & 7) + ((lane >> 3) & 1) * 8;
    const int cHA = lane >> 4;
    const int rowOffB = ((lane >> 4) << 3) + (lane & 7);
    const int cHB = (lane >> 3) & 1;

    const int r0 = lwid * 16 + (lane >> 2);
    const int r1 = r0 + 8;
    const int rn0 = r0 >> 3, cn0 = r0 & 7;
    const int rn1 = r1 >> 3, cn1 = r1 & 7;
    const int li = (wi == 15), lj = (wj == 15);
    const int lab0 = (li ? (rn0 < 4 ? 1 : 2) : 0) * 3 + (lj ? (cn0 < 4 ? 1 : 2) : 0);
    const int lab1 = (li ? (rn1 < 4 ? 1 : 2) : 0) * 3 + (lj ? (cn1 < 4 ? 1 : 2) : 0);

    for (int h = 0; h < NHEADS; h++) {
        const unsigned qh = qb + h * 8192, kh = kb + h * 8192, vh = vb + h * 8192;

        float sacc[8][4];
#pragma unroll
        for (int i = 0; i < 8; i++)
#pragma unroll
            for (int j = 0; j < 4; j++) sacc[i][j] = 0.f;

#pragma unroll
        for (int kk = 0; kk < 2; kk++) {
            unsigned aq[4];
            {
                int row = wro + lwid * 16 + rowOffA;
                int ch = kk * 2 + cHA;
                ldsm4(aq, qh + row * 64 + ((ch ^ ((row >> 1) & 3)) << 4));
            }
#pragma unroll
            for (int nt2 = 0; nt2 < 4; nt2++) {
                unsigned bk[4];
                int row = wro + nt2 * 16 + rowOffB;
                int ch = kk * 2 + cHB;
                ldsm4(bk, kh + row * 64 + ((ch ^ ((row >> 1) & 3)) << 4));
                mma_bf16(sacc[nt2 * 2 + 0], aq, &bk[0]);
                mma_bf16(sacc[nt2 * 2 + 1], aq, &bk[2]);
            }
        }

#pragma unroll
        for (int nt = 0; nt < 8; nt++) {
#pragma unroll
            for (int j = 0; j < 4; j++) {
                int m = nt * 8 + (lane & 3) * 2 + (j & 1);
                int rm = m >> 3, cm = m & 7;
                int labm = (li ? (rm < 4 ? 1 : 2) : 0) * 3 + (lj ? (cm < 4 ? 1 : 2) : 0);
                float v = sacc[nt][j] * scale;
                int idx;
                if (j < 2) {
                    idx = (rn0 - rm + 7) * 15 + (cn0 - cm + 7);
                    v += *(float*)(dsm + FQ_BIAS + (idx * 6 + h) * 4);
                    if (labm != lab0) v -= 100.f;
                } else {
                    idx = (rn1 - rm + 7) * 15 + (cn1 - cm + 7);
                    v += *(float*)(dsm + FQ_BIAS + (idx * 6 + h) * 4);
                    if (labm != lab1) v -= 100.f;
                }
                sacc[nt][j] = v;
            }
        }

        float mx0 = -1e30f, mx1 = -1e30f;
#pragma unroll
        for (int nt = 0; nt < 8; nt++) {
            mx0 = fmaxf(mx0, fmaxf(sacc[nt][0], sacc[nt][1]));
            mx1 = fmaxf(mx1, fmaxf(sacc[nt][2], sacc[nt][3]));
        }
        mx0 = fmaxf(mx0, __shfl_xor_sync(0xffffffffu, mx0, 1));
        mx0 = fmaxf(mx0, __shfl_xor_sync(0xffffffffu, mx0, 2));
        mx1 = fmaxf(mx1, __shfl_xor_sync(0xffffffffu, mx1, 1));
        mx1 = fmaxf(mx1, __shfl_xor_sync(0xffffffffu, mx1, 2));
        float sum0 = 0.f, sum1 = 0.f;
#pragma unroll
        for (int nt = 0; nt < 8; nt++) {
            sacc[nt][0] = __expf(sacc[nt][0] - mx0); sum0 += sacc[nt][0];
            sacc[nt][1] = __expf(sacc[nt][1] - mx0); sum0 += sacc[nt][1];
            sacc[nt][2] = __expf(sacc[nt][2] - mx1); sum1 += sacc[nt][2];
            sacc[nt][3] = __expf(sacc[nt][3] - mx1); sum1 += sacc[nt][3];
        }
        sum0 += __shfl_xor_sync(0xffffffffu, sum0, 1);
        sum0 += __shfl_xor_sync(0xffffffffu, sum0, 2);
        sum1 += __shfl_xor_sync(0xffffffffu, sum1, 1);
        sum1 += __shfl_xor_sync(0xffffffffu, sum1, 2);
        const float inv0 = 1.f / sum0, inv1 = 1.f / sum1;

        float oacc[4][4];
#pragma unroll
        for (int i = 0; i < 4; i++)
#pragma unroll
            for (int j = 0; j < 4; j++) oacc[i][j] = 0.f;

#pragma unroll
        for (int kk2 = 0; kk2 < 4; kk2++) {
            unsigned ap[4];
            ap[0] = packbf(sacc[2 * kk2][0], sacc[2 * kk2][1]);
            ap[1] = packbf(sacc[2 * kk2][2], sacc[2 * kk2][3]);
            ap[2] = packbf(sacc[2 * kk2 + 1][0], sacc[2 * kk2 + 1][1]);
            ap[3] = packbf(sacc[2 * kk2 + 1][2], sacc[2 * kk2 + 1][3]);
#pragma unroll
            for (int nt2 = 0; nt2 < 2; nt2++) {
                unsigned bv[4];
                int row = wro + kk2 * 16 + (lane & 7) + ((lane >> 3) & 1) * 8;
                int ch = 2 * nt2 + (lane >> 4);
                ldsm4t(bv, vh + row * 64 + ((ch ^ ((row >> 1) & 3)) << 4));
                mma_bf16(oacc[nt2 * 2 + 0], ap, &bv[0]);
                mma_bf16(oacc[nt2 * 2 + 1], ap, &bv[2]);
            }
        }

        const int grow0 = wro + r0;
        const int grow1 = wro + r1;
        const int d0 = (lane & 3) * 2;
#pragma unroll
        for (int nt = 0; nt < 4; nt++) {
            const int d = nt * 8 + d0;
            unsigned p0 = packbf(oacc[nt][0] * inv0, oacc[nt][1] * inv0);
            unsigned p1 = packbf(oacc[nt][2] * inv1, oacc[nt][3] * inv1);
            asm volatile("st.shared.b32 [%0], %1;"
                         :: "r"(qh + swz(grow0, d >> 3) + (d & 7) * 2), "r"(p0) : "memory");
            asm volatile("st.shared.b32 [%0], %1;"
                         :: "r"(qh + swz(grow1, d >> 3) + (d & 7) * 2), "r"(p1) : "memory");
        }
    }
    cp_wait<0>();
    __syncthreads();

    // ---- phase 3: proj GEMM, scatter + residual -> x2 ----
    {
#pragma unroll
        for (int p = 0; p < 3; p++) {
            cp16s(sb + FQ_SMB + p * 4096 + swz(brow, bch),
                  Pt + (size_t)brow * 192 + p * 32 + bch * 8);
            cp_commit();
        }
        int pn = 0, pk = 3, pmod = 3, cmod = 0;
        for (int nc = 0; nc < 3; nc++) {
            float acc[2][4][4];
#pragma unroll
            for (int i = 0; i < 2; i++)
#pragma unroll
                for (int j = 0; j < 4; j++)
#pragma unroll
                    for (int l = 0; l < 4; l++) acc[i][j][l] = 0.f;

#pragma unroll
            for (int k = 0; k < 6; k++) {
                cp_wait<2>();
                __syncthreads();
                if (pn < 3) {
                    cp16s(sb + FQ_SMB + pmod * 4096 + swz(brow, bch),
                          Pt + (size_t)(pn * 64 + brow) * 192 + pk * 32 + bch * 8);
                }
                cp_commit();
                pmod = (pmod + 1) & 3;
                if (++pk == 6) { pk = 0; pn++; }

                const unsigned As_u = qb + k * 8192;
                const unsigned Bs_u = sb + FQ_SMB + cmod * 4096;
                cmod = (cmod + 1) & 3;
#pragma unroll
                for (int s = 0; s < 2; s++) {
                    unsigned af[2][4], bf[2][4];
                    const int chA = 2 * s + cHalfA;
                    const int chB = 2 * s + cHalfB;
#pragma unroll
                    for (int t = 0; t < 2; t++) {
                        int row = rowA0 + t * 16;
                        ldsm4(af[t], As_u + row * 64 + ((chA ^ ((row >> 1) & 3)) << 4));
                    }
#pragma unroll
                    for (int t = 0; t < 2; t++) {
                        int row = rowB0 + t * 16;
                        ldsm4(bf[t], Bs_u + row * 64 + ((chB ^ ((row >> 1) & 3)) << 4));
                    }
#pragma unroll
                    for (int mt = 0; mt < 2; mt++)
#pragma unroll
                        for (int nt = 0; nt < 4; nt++)
                            mma_bf16(acc[mt][nt], af[mt], &bf[nt >> 1][(nt & 1) * 2]);
                }
            }

#pragma unroll
            for (int mt = 0; mt < 2; mt++) {
#pragma unroll
                for (int nt = 0; nt < 4; nt++) {
                    const float* c = acc[mt][nt];
                    const int col = nc * 64 + nw * 32 + nt * 8 + (lane & 3) * 2;
                    const float bx = pbias[col], by = pbias[col + 1];
                    const int rbase = mw * 32 + mt * 16 + (lane >> 2);
#pragma unroll
                    for (int half = 0; half < 2; half++) {
                        int m = rbase + half * 8;
                        int dst = win_to_tok(m0 + m);
                        size_t idx = (size_t)dst * CDIM + col;
                        float2 res = *(const float2*)&xres[idx];
                        *(float2*)&x2out[idx] = make_float2(c[half * 2] + bx + res.x,
                                                            c[half * 2 + 1] + by + res.y);
                    }
                }
            }
        }
    }
}

// ---- mma.sync bf16 GEMM 128x64 (MLP2), 3-stage pipeline ----
#define BUFSZ ((128 + 64) * 64)
template <int EPI, int NSTEPS, typename OutT>
__global__ void __launch_bounds__(256) gemm_bf16(
        const __nv_bfloat16* __restrict__ A, const __nv_bfloat16* __restrict__ Bt,
        const float* __restrict__ bias, OutT* __restrict__ C,
        const float* __restrict__ R, int N) {
    __shared__ __align__(16) unsigned char smem[3 * BUFSZ];
    const int K = NSTEPS * 32;

    const int m0 = blockIdx.y * 128;
    const int n0 = blockIdx.x * 64;
    const int tid = threadIdx.x;
    const int lane = tid & 31;
    const int wid = tid >> 5;
    const int mw = wid & 3;
    const int nw = wid >> 2;

    const int a_row = tid >> 1;
    const int a_c0 = (tid & 1) * 2;
    const int b_row = tid >> 2;
    const int b_c = tid & 3;
    const __nv_bfloat16* aptr = A + (size_t)(m0 + a_row) * K + a_c0 * 8;
    const __nv_bfloat16* bptr = Bt + (size_t)(n0 + b_row) * K + b_c * 8;
    const int sA0 = swz(a_row, a_c0), sA1 = swz(a_row, a_c0 + 1), sB = swz(b_row, b_c);

    float acc[2][4][4];
#pragma unroll
    for (int i = 0; i < 2; i++)
#pragma unroll
        for (int j = 0; j < 4; j++)
#pragma unroll
            for (int l = 0; l < 4; l++) acc[i][j][l] = 0.f;

    const int rowA0 = mw * 32 + (lane & 7) + ((lane >> 3) & 1) * 8;
    const int cHalfA = lane >> 4;
    const int rowB0 = nw * 32 + ((lane >> 4) << 3) + (lane & 7);
    const int cHalfB = (lane >> 3) & 1;

#pragma unroll
    for (int p = 0; p < 2; p++) {
        unsigned char* As = smem + p * BUFSZ;
        unsigned char* Bs = As + 128 * 64;
        cp16(As + sA0, aptr + p * 32);
        cp16(As + sA1, aptr + p * 32 + 8);
        cp16(Bs + sB, bptr + p * 32);
        cp_commit();
    }

#pragma unroll
    for (int step = 0; step < NSTEPS; step++) {
        if (step == NSTEPS - 1) cp_wait<0>(); else cp_wait<1>();
        __syncthreads();

        if (step + 2 < NSTEPS) {
            unsigned char* As = smem + ((step + 2) % 3) * BUFSZ;
            unsigned char* Bs = As + 128 * 64;
            cp16(As + sA0, aptr + (step + 2) * 32);
            cp16(As + sA1, aptr + (step + 2) * 32 + 8);
            cp16(Bs + sB, bptr + (step + 2) * 32);
            cp_commit();
        }

        const unsigned As_u = scvta(smem + (step % 3) * BUFSZ);
        const unsigned Bs_u = As_u + 128 * 64;
#pragma unroll
        for (int s = 0; s < 2; s++) {
            unsigned af[2][4], bf[2][4];
            const int chA = 2 * s + cHalfA;
            const int chB = 2 * s + cHalfB;
#pragma unroll
            for (int t = 0; t < 2; t++) {
                int row = rowA0 + t * 16;
                ldsm4(af[t], As_u + row * 64 + ((chA ^ ((row >> 1) & 3)) << 4));
            }
#pragma unroll
            for (int t = 0; t < 2; t++) {
                int row = rowB0 + t * 16;
                ldsm4(bf[t], Bs_u + row * 64 + ((chB ^ ((row >> 1) & 3)) << 4));
            }
#pragma unroll
            for (int mt = 0; mt < 2; mt++)
#pragma unroll
                for (int nt = 0; nt < 4; nt++)
                    mma_bf16(acc[mt][nt], af[mt], &bf[nt >> 1][(nt & 1) * 2]);
        }
    }

#pragma unroll
    for (int mt = 0; mt < 2; mt++) {
#pragma unroll
        for (int nt = 0; nt < 4; nt++) {
            const float* c = acc[mt][nt];
            const int col = n0 + nw * 32 + nt * 8 + (lane & 3) * 2;
            const float bx = bias[col], by = bias[col + 1];
            const int rbase = m0 + mw * 32 + mt * 16 + (lane >> 2);
#pragma unroll
            for (int half = 0; half < 2; half++) {
                int m = rbase + half * 8;
                float vx = c[half * 2 + 0] + bx;
                float vy = c[half * 2 + 1] + by;
                if (EPI == 1) { vx = gelu_fast(vx); vy = gelu_fast(vy); }
                if (EPI == 3) {
                    size_t idx = (size_t)m * N + col;
                    float2 res = *(const float2*)&R[idx];
                    *(float2*)((float*)C + idx) = make_float2(vx + res.x, vy + res.y);
                } else {
                    __nv_bfloat162 o = __floats2bfloat162_rn(vx, vy);
                    *(__nv_bfloat162*)((__nv_bfloat16*)C + (size_t)m * N + col) = o;
                }
            }
        }
    }
}

// ---- wide bf16 GEMM 128x128x32 (MLP1: K=192, GELU, bf16 out) ----
#define WBUF (256 * 64)
__global__ void __launch_bounds__(256) gemm_wide_gelu(
        const __nv_bfloat16* __restrict__ A, const __nv_bfloat16* __restrict__ Bt,
        const float* __restrict__ bias, __nv_bfloat16* __restrict__ C, int N) {
    __shared__ __align__(16) unsigned char smem[3 * WBUF];
    const int K = 192, NSTEPS = 6;

    const int m0 = blockIdx.y * 128;
    const int n0 = blockIdx.x * 128;
    const int tid = threadIdx.x;
    const int lane = tid & 31;
    const int wid = tid >> 5;
    const int mw = wid & 3;
    const int nw = wid >> 2;

    const int l_row = tid >> 1;
    const int l_c0 = (tid & 1) * 2;
    const __nv_bfloat16* aptr = A + (size_t)(m0 + l_row) * K + l_c0 * 8;
    const __nv_bfloat16* bptr = Bt + (size_t)(n0 + l_row) * K + l_c0 * 8;
    const int sL0 = swz(l_row, l_c0), sL1 = swz(l_row, l_c0 + 1);

    float acc[2][8][4];
#pragma unroll
    for (int i = 0; i < 2; i++)
#pragma unroll
        for (int j = 0; j < 8; j++)
#pragma unroll
            for (int l = 0; l < 4; l++) acc[i][j][l] = 0.f;

    const int rowA0 = mw * 32 + (lane & 7) + ((lane >> 3) & 1) * 8;
    const int cHalfA = lane >> 4;
    const int rowB0 = nw * 64 + ((lane >> 4) << 3) + (lane & 7);
    const int cHalfB = (lane >> 3) & 1;

#pragma unroll
    for (int p = 0; p < 2; p++) {
        unsigned char* As = smem + p * WBUF;
        unsigned char* Bs = As + 128 * 64;
        cp16(As + sL0, aptr + p * 32);
        cp16(As + sL1, aptr + p * 32 + 8);
        cp16(Bs + sL0, bptr + p * 32);
        cp16(Bs + sL1, bptr + p * 32 + 8);
        cp_commit();
    }

#pragma unroll
    for (int step = 0; step < NSTEPS; step++) {
        if (step == NSTEPS - 1) cp_wait<0>(); else cp_wait<1>();
        __syncthreads();

        if (step + 2 < NSTEPS) {
            unsigned char* As = smem + ((step + 2) % 3) * WBUF;
            unsigned char* Bs = As + 128 * 64;
            cp16(As + sL0, aptr + (step + 2) * 32);
            cp16(As + sL1, aptr + (step + 2) * 32 + 8);
            cp16(Bs + sL0, bptr + (step + 2) * 32);
            cp16(Bs + sL1, bptr + (step + 2) * 32 + 8);
            cp_commit();
        }

        const unsigned As_u = scvta(smem + (step % 3) * WBUF);
        const unsigned Bs_u = As_u + 128 * 64;
#pragma unroll
        for (int s = 0; s < 2; s++) {
            unsigned af[2][4], bf[4][4];
            const int chA = 2 * s + cHalfA;
            const int chB = 2 * s + cHalfB;
#pragma unroll
            for (int t = 0; t < 2; t++) {
                int row = rowA0 + t * 16;
                ldsm4(af[t], As_u + row * 64 + ((chA ^ ((row >> 1) & 3)) << 4));
            }
#pragma unroll
            for (int t = 0; t < 4; t++) {
                int row = rowB0 + t * 16;
                ldsm4(bf[t], Bs_u + row * 64 + ((chB ^ ((row >> 1) & 3)) << 4));
            }
#pragma unroll
            for (int mt = 0; mt < 2; mt++)
#pragma unroll
                for (int nt = 0; nt < 8; nt++)
                    mma_bf16(acc[mt][nt], af[mt], &bf[nt >> 1][(nt & 1) * 2]);
        }
    }

#pragma unroll
    for (int mt = 0; mt < 2; mt++) {
#pragma unroll
        for (int nt = 0; nt < 8; nt++) {
            const float* c = acc[mt][nt];
            const int col = n0 + nw * 64 + nt * 8 + (lane & 3) * 2;
            const float bx = bias[col], by = bias[col + 1];
            const int rbase = m0 + mw * 32 + mt * 16 + (lane >> 2);
#pragma unroll
            for (int half = 0; half < 2; half++) {
                int m = rbase + half * 8;
                float vx = gelu_fast(c[half * 2 + 0] + bx);
                float vy = gelu_fast(c[half * 2 + 1] + by);
                *(unsigned*)(C + (size_t)m * N + col) = packbf(vx, vy);
            }
        }
    }
}

// -------------------- launch --------------------
extern "C" void kernel_launch(void* const* d_in, const int* in_sizes, int n_in,
                              void* d_out, int out_size) {
    (void)in_sizes; (void)n_in; (void)out_size;
    const float* x      = (const float*)d_in[0];
    const float* qkv_w  = (const float*)d_in[3];
    const float* qkv_b  = (const float*)d_in[4];
    const float* proj_w = (const float*)d_in[5];
    const float* proj_b = (const float*)d_in[6];
    const float* rpb    = (const float*)d_in[7];
    const float* n1w    = (const float*)d_in[8];
    const float* n1b    = (const float*)d_in[9];
    const float* n2w    = (const float*)d_in[10];
    const float* n2b    = (const float*)d_in[11];
    const float* w1     = (const float*)d_in[12];
    const float* b1     = (const float*)d_in[13];
    const float* w2     = (const float*)d_in[14];
    const float* b2     = (const float*)d_in[15];
    float* out = (float*)d_out;

    __nv_bfloat16 *winln, *h2, *mlpg;
    __nv_bfloat16 *qkvw_t, *projw_t, *w1_t, *w2_t;
    float* x2;
    cudaGetSymbolAddress((void**)&winln,  g_winln);
    cudaGetSymbolAddress((void**)&x2,     g_x2);
    cudaGetSymbolAddress((void**)&h2,     g_h2);
    cudaGetSymbolAddress((void**)&mlpg,   g_mlp);
    cudaGetSymbolAddress((void**)&qkvw_t, g_qkvw_t);
    cudaGetSymbolAddress((void**)&projw_t,g_projw_t);
    cudaGetSymbolAddress((void**)&w1_t,   g_w1_t);
    cudaGetSymbolAddress((void**)&w2_t,   g_w2_t);

    static bool attr_set = false;
    if (!attr_set) {
        cudaFuncSetAttribute(qkv_attn_proj, cudaFuncAttributeMaxDynamicSharedMemorySize, FQ_TOTAL);
        attr_set = true;
    }

    wconv_all<<<(WC4 + 255) / 256, 256>>>(qkv_w, proj_w, w1, w2);

    // 1. LN1 + shift + window gather (fp32 -> bf16)
    ln_kernel<true><<<TOKENS / 8, 256>>>(x, winln, n1w, n1b);
    // 2. fused QKV GEMM + attention + proj + scatter + residual -> fp32 x2
    qkv_attn_proj<<<NWIN / 2, 256, FQ_TOTAL>>>(winln, qkvw_t, qkv_b, rpb,
                                               projw_t, proj_b, x, x2);
    // 3. LN2 (fp32 -> bf16)
    ln_kernel<false><<<TOKENS / 8, 256>>>(x2, h2, n2w, n2b);
    // 4. MLP1 + fast GELU -> bf16 (wide 128x128 tiles)
    gemm_wide_gelu<<<dim3(6, TOKENS / 128), 256>>>(h2, w1_t, b1, mlpg, HIDDEN);
    // 5. MLP2 + residual -> fp32 out
    gemm_bf16<3, 24, float><<<dim3(3, TOKENS / 128), 256>>>(
        mlpg, w2_t, b2, out, x2, CDIM);
}